// round 17
// baseline (speedup 1.0000x reference)
#include <cuda_runtime.h>
#include <cstdint>

// Problem constants (fixed by reference)
#define BS   1024
#define NSEQ 32
#define NBOX 128
#define NCTX 5
#define MAXC 4

// One warp per (it,b) task; each warp ALSO copies its share of rows
// [32*it/L, 32*(it+1)/L) of batch b (partitions all rows across it=0..L-1).
// Warp pipeline: issue hop-1 index loads + ballot column + copy-row loads at
// t0 (all independent) -> ballot -> copy stores (their wait hides the index
// wait) -> compute section with the chain already hot.
// Copy rows are LOADED unconditionally (issue at t0) and STORED only if not
// a parent row; parent rows are written exclusively by their compute warp.
//
// R17 change: __launch_bounds__(256, 6) caps regs at 40 (was 48) -> 6
// blocks/SM instead of 5, buying warp residency for this latency-bound body.
//
// Fully parallel: children always have larger indices than parents; parents
// ascend & are unique per batch, so every read in the sequential reference
// sees the ORIGINAL ent_attn.
__global__ __launch_bounds__(256, 6) void topdown_fused_kernel(
    const float* __restrict__ ent,   // [BS,NSEQ,NBOX]
    const float* __restrict__ spo,   // [BS,NSEQ,NBOX,NCTX]
    const int*   __restrict__ ctx,   // [BS,NSEQ,NBOX,NCTX]
    const float* __restrict__ roi,   // [BS,NSEQ,NBOX,NCTX]
    const int*   __restrict__ rcls,  // [BS,NBOX]
    const float* __restrict__ w,     // [BS,NSEQ,NBOX]
    const int*   __restrict__ pidx,  // [L,BS]
    const float* __restrict__ pval,  // [L,BS]
    const int*   __restrict__ cidx,  // [L,BS,MAXC]
    const float* __restrict__ cval,  // [L,BS,MAXC]
    const int*   __restrict__ eidx,  // [L,BS,MAXC]
    const int*   __restrict__ fsmp,  // [L,BS]
    const int*   __restrict__ fslt,  // [L,BS]
    float*       __restrict__ out,   // [BS,NSEQ,NBOX]
    int n_tasks, int L)
{
    const int warp = (blockIdx.x * blockDim.x + threadIdx.x) >> 5;
    const int lane = threadIdx.x & 31;
    if (warp >= n_tasks) return;
    const int it = warp >> 10;          // / BS
    const int b  = warp & (BS - 1);     // % BS
    const int base = it * BS + b;

    // ---- t0: hop-1 index loads (independent; issued together) ----
    const float pv  = pval[base];
    const int   r   = pidx[base];
    const int   c0  = cidx[base * MAXC + 0];
    const float cv0 = cval[base * MAXC + 0];
    const int   e0  = eidx[base * MAXC + 0];
    const int   fs  = fsmp[base];
    const int   fl  = fslt[base];

    // ballot column (lane = iteration)
    int   pb = -1;
    float vb = 0.f;
    if (lane < L) {
        pb = pidx[lane * BS + b];
        vb = pval[lane * BS + b];
    }

    // ---- t0: copy-row loads, unconditional (rows r0..r1-1 of batch b) ----
    const int r0 = (NSEQ * it) / L;
    const int r1 = (NSEQ * (it + 1)) / L;
    const float4* entb = (const float4*)(ent + (size_t)b * NSEQ * NBOX);
    float4*       outb = (float4*)((float*)out + (size_t)b * NSEQ * NBOX);

    float4 cvv[4];
    #pragma unroll
    for (int q = 0; q < 4; q++) {
        const int rr = r0 + q;
        if (rr < r1) cvv[q] = entb[rr * 32 + lane];
    }

    // ---- parent-row bitmask (waits only on the ballot column) ----
    unsigned bit = 0;
    if (lane < L && vb > 0.f) bit = 1u << pb;
    const unsigned rowmask = __reduce_or_sync(0xffffffffu, bit);

    // ---- copy stores: wait for copy data overlaps hop-1 index wait ----
    #pragma unroll
    for (int q = 0; q < 4; q++) {
        const int rr = r0 + q;
        if (rr < r1 && !((rowmask >> rr) & 1u))
            __stcs(outb + rr * 32 + lane, cvv[q]);
    }
    // safety tail for L < 8 (not expected in this dataset)
    for (int rr = r0 + 4; rr < r1; rr++) {
        if (!((rowmask >> rr) & 1u)) {
            const float4 v = entb[rr * 32 + lane];
            __stcs(outb + rr * 32 + lane, v);
        }
    }

    if (pv <= 0.f) return;              // warp-uniform; copy duty done

    // ---- hop 2: fe; addresses for all row reads (indices already hot) ----
    const int fe = eidx[(it * BS + fs) * MAXC + fl];

    const float* entc   = ent  + ((size_t)b * NSEQ + c0) * NBOX;
    const float* spor   = spo  + ((size_t)b * NSEQ + e0) * NBOX * NCTX;
    const float* roir   = roi  + ((size_t)b * NSEQ + e0) * NBOX * NCTX;
    const int*   clsrow = rcls + (size_t)b * NBOX;

    // hop 3 issued before the reduction, consumed after it
    int cols[NCTX];
    const int* cbase = ctx + (((size_t)fs * NSEQ + fe) * NBOX) * NCTX;
    #pragma unroll
    for (int k = 0; k < NCTX; k++) cols[k] = cbase[k];

    // --- transfer[k] = cv0 * sum_box ent[b,c0,box]*cls*spo[b,e0,box,k]*roi[b,e0,box,k] + 1e-6 ---
    float t0 = 0.f, t1 = 0.f, t2 = 0.f, t3 = 0.f, t4 = 0.f;
    #pragma unroll
    for (int q = 0; q < NBOX / 32; q++) {
        const int box = lane + q * 32;
        float ca = entc[box];
        if (clsrow[box] == -1) ca = 0.f;
        const float* s  = spor + box * NCTX;
        const float* mr = roir + box * NCTX;
        t0 += ca * __ldcs(s + 0) * __ldcs(mr + 0);
        t1 += ca * __ldcs(s + 1) * __ldcs(mr + 1);
        t2 += ca * __ldcs(s + 2) * __ldcs(mr + 2);
        t3 += ca * __ldcs(s + 3) * __ldcs(mr + 3);
        t4 += ca * __ldcs(s + 4) * __ldcs(mr + 4);
    }
    #pragma unroll
    for (int o = 16; o > 0; o >>= 1) {
        t0 += __shfl_xor_sync(0xffffffffu, t0, o);
        t1 += __shfl_xor_sync(0xffffffffu, t1, o);
        t2 += __shfl_xor_sync(0xffffffffu, t2, o);
        t3 += __shfl_xor_sync(0xffffffffu, t3, o);
        t4 += __shfl_xor_sync(0xffffffffu, t4, o);
    }
    float tr[NCTX];
    tr[0] = cv0 * t0 + 1e-6f;
    tr[1] = cv0 * t1 + 1e-6f;
    tr[2] = cv0 * t2 + 1e-6f;
    tr[3] = cv0 * t3 + 1e-6f;
    tr[4] = cv0 * t4 + 1e-6f;

    // --- row update: each lane owns 4 consecutive boxes of the parent row ---
    const float4 sub = entb[r * 32 + lane];
    const float4 wv  = __ldcs(((const float4*)(w + ((size_t)b * NSEQ + r) * NBOX)) + lane);
    const int4   cl  = ((const int4*)clsrow)[lane];

    float su[4]  = {sub.x, sub.y, sub.z, sub.w};
    float wa[4]  = {wv.x, wv.y, wv.z, wv.w};
    int   cla[4] = {cl.x, cl.y, cl.z, cl.w};

    float u[4];
    float mx = 0.f;
    #pragma unroll
    for (int q = 0; q < 4; q++) {
        const int box = lane * 4 + q;
        float add = 1e-6f;
        #pragma unroll
        for (int k = 0; k < NCTX; k++)
            if (cols[k] == box) add = tr[k];
        u[q] = su[q] + add * wa[q];
        mx = fmaxf(mx, fabsf(u[q]));
    }
    #pragma unroll
    for (int o = 16; o > 0; o >>= 1)
        mx = fmaxf(mx, __shfl_xor_sync(0xffffffffu, mx, o));
    const float d = (mx <= 1.f) ? 1.f : mx;

    float rr4[4];
    #pragma unroll
    for (int q = 0; q < 4; q++) {
        float vvv = u[q] / d;
        if (cla[q] == -1) vvv = -1.0f;
        rr4[q] = vvv;
    }
    float4 res;
    res.x = rr4[0]; res.y = rr4[1]; res.z = rr4[2]; res.w = rr4[3];
    __stcs(outb + r * 32 + lane, res);
}

extern "C" void kernel_launch(void* const* d_in, const int* in_sizes, int n_in,
                              void* d_out, int out_size) {
    const float* ent  = (const float*)d_in[0];   // ent_attn
    const float* spo  = (const float*)d_in[1];   // spo_attn
    const int*   ctx  = (const int*)  d_in[2];   // ctx_idx_adjusted
    const float* roi  = (const float*)d_in[3];   // roi_mask
    const int*   rcls = (const int*)  d_in[4];   // roi_cls
    const float* w    = (const float*)d_in[5];   // weight_on_children
    const int*   pidx = (const int*)  d_in[6];   // parent_idx [L,BS]
    const float* pval = (const float*)d_in[7];   // parent_valid
    const int*   cidx = (const int*)  d_in[8];   // child_idx
    const float* cval = (const float*)d_in[9];   // child_valid
    const int*   eidx = (const int*)  d_in[10];  // edge_idx
    const int*   fsmp = (const int*)  d_in[11];  // flat_sample
    const int*   fslt = (const int*)  d_in[12];  // flat_slot

    const int L = in_sizes[6] / BS;
    const int n_tasks = L * BS;

    const int threads = 256;                              // 8 warps/block
    const int blocks = (n_tasks * 32 + threads - 1) / threads;

    topdown_fused_kernel<<<blocks, threads>>>(
        ent, spo, ctx, roi, rcls, w,
        pidx, pval, cidx, cval, eidx, fsmp, fslt,
        (float*)d_out, n_tasks, L);
}